// round 8
// baseline (speedup 1.0000x reference)
#include <cuda_runtime.h>
#include <cuda_bf16.h>
#include <mma.h>

using namespace nvcuda;

// ---------------- problem constants ----------------
#define B_    2
#define S_    2048
#define DIM_  5120
#define H_    40
#define KVH_  8
#define HD_   128
#define NREP_ 5
#define M_    (B_*S_)        // 4096
#define KVDIM_ (KVH_*HD_)    // 1024
#define WINDOW_ 1024
static const float SCALE_F = (float)(1.2079441541679836 / 11.313708498984760390); // mscale / sqrt(128)

// ---------------- scratch (device globals; no allocations allowed) ----------------
__device__ __align__(256) float g_xq[(size_t)M_*DIM_];
__device__ __align__(256) float g_xk[(size_t)M_*KVDIM_];
__device__ __align__(256) float g_xv[(size_t)M_*KVDIM_];
__device__ __align__(256) float g_q [(size_t)B_*H_*S_*HD_];
__device__ __align__(256) float g_k [(size_t)B_*KVH_*S_*HD_];
__device__ __align__(256) float g_v [(size_t)B_*KVH_*S_*HD_];
__device__ __align__(256) float g_attn[(size_t)M_*DIM_];

// ---------------- tf32 WMMA GEMM: C[M,N] = A[M,K] @ B[K,N], all row-major fp32 ----------------
// Double-buffered smem + register prefetch. One sync per K-step.
#define BM 128
#define BN 128
#define BK 32
#define BKP 36
#define BNP 132
#define A_TILE (BM * BKP)               // 4608 floats
#define B_TILE (BK * BNP)               // 4224 floats
#define GEMM_SMEM_BYTES ((2 * A_TILE + 2 * B_TILE) * 4)   // 70,656 B

__global__ __launch_bounds__(256) void gemm_tf32(const float* __restrict__ A,
                                                 const float* __restrict__ Bm,
                                                 float* __restrict__ C,
                                                 int M, int N, int K)
{
    extern __shared__ float smem[];
    float* AsBase = smem;                 // [2][A_TILE]
    float* BsBase = smem + 2 * A_TILE;    // [2][B_TILE]

    const int tid = threadIdx.x;
    const int w   = tid >> 5;
    const int wm  = w & 3;      // 0..3 -> 32-row slab
    const int wn  = w >> 2;     // 0..1 -> 64-col slab
    const int bm0 = blockIdx.y * BM;
    const int bn0 = blockIdx.x * BN;

    wmma::fragment<wmma::accumulator, 16, 16, 8, float> acc[2][4];
    #pragma unroll
    for (int i = 0; i < 2; i++)
        #pragma unroll
        for (int j = 0; j < 4; j++)
            wmma::fill_fragment(acc[i][j], 0.0f);

    // per-thread tile coordinates (fixed across iterations)
    // A tile: 128x32, 4 float4 per thread
    int ar[4], ac[4];
    // B tile: 32x128, 4 float4 per thread
    int br[4], bc[4];
    #pragma unroll
    for (int t = 0; t < 4; t++) {
        int ia = tid + t * 256;
        ar[t] = ia >> 3;  ac[t] = (ia & 7) << 2;
        br[t] = ia >> 5;  bc[t] = (ia & 31) << 2;
    }

    // ---- prologue: stage k0 = 0 directly ----
    {
        #pragma unroll
        for (int t = 0; t < 4; t++) {
            float4 v = *(const float4*)(A + (size_t)(bm0 + ar[t]) * K + ac[t]);
            float* dst = AsBase + ar[t] * BKP + ac[t];
            dst[0] = wmma::__float_to_tf32(v.x);
            dst[1] = wmma::__float_to_tf32(v.y);
            dst[2] = wmma::__float_to_tf32(v.z);
            dst[3] = wmma::__float_to_tf32(v.w);
        }
        #pragma unroll
        for (int t = 0; t < 4; t++) {
            float4 v = *(const float4*)(Bm + (size_t)br[t] * N + bn0 + bc[t]);
            float* dst = BsBase + br[t] * BNP + bc[t];
            dst[0] = wmma::__float_to_tf32(v.x);
            dst[1] = wmma::__float_to_tf32(v.y);
            dst[2] = wmma::__float_to_tf32(v.z);
            dst[3] = wmma::__float_to_tf32(v.w);
        }
    }
    __syncthreads();

    int buf = 0;
    for (int k0 = 0; k0 < K; k0 += BK) {
        const bool has_next = (k0 + BK) < K;
        float4 ra[4], rb[4];
        if (has_next) {
            const int kn = k0 + BK;
            #pragma unroll
            for (int t = 0; t < 4; t++)
                ra[t] = *(const float4*)(A + (size_t)(bm0 + ar[t]) * K + kn + ac[t]);
            #pragma unroll
            for (int t = 0; t < 4; t++)
                rb[t] = *(const float4*)(Bm + (size_t)(kn + br[t]) * N + bn0 + bc[t]);
        }

        const float* As = AsBase + buf * A_TILE;
        const float* Bs = BsBase + buf * B_TILE;
        #pragma unroll
        for (int kk = 0; kk < BK; kk += 8) {
            wmma::fragment<wmma::matrix_a, 16, 16, 8, wmma::precision::tf32, wmma::row_major> af[2];
            wmma::fragment<wmma::matrix_b, 16, 16, 8, wmma::precision::tf32, wmma::row_major> bf[4];
            #pragma unroll
            for (int i = 0; i < 2; i++)
                wmma::load_matrix_sync(af[i], As + (wm * 32 + i * 16) * BKP + kk, BKP);
            #pragma unroll
            for (int j = 0; j < 4; j++)
                wmma::load_matrix_sync(bf[j], Bs + kk * BNP + wn * 64 + j * 16, BNP);
            #pragma unroll
            for (int i = 0; i < 2; i++)
                #pragma unroll
                for (int j = 0; j < 4; j++)
                    wmma::mma_sync(acc[i][j], af[i], bf[j], acc[i][j]);
        }

        if (has_next) {
            float* An = AsBase + (1 - buf) * A_TILE;
            float* Bn = BsBase + (1 - buf) * B_TILE;
            #pragma unroll
            for (int t = 0; t < 4; t++) {
                float* dst = An + ar[t] * BKP + ac[t];
                dst[0] = wmma::__float_to_tf32(ra[t].x);
                dst[1] = wmma::__float_to_tf32(ra[t].y);
                dst[2] = wmma::__float_to_tf32(ra[t].z);
                dst[3] = wmma::__float_to_tf32(ra[t].w);
            }
            #pragma unroll
            for (int t = 0; t < 4; t++) {
                float* dst = Bn + br[t] * BNP + bc[t];
                dst[0] = wmma::__float_to_tf32(rb[t].x);
                dst[1] = wmma::__float_to_tf32(rb[t].y);
                dst[2] = wmma::__float_to_tf32(rb[t].z);
                dst[3] = wmma::__float_to_tf32(rb[t].w);
            }
        }
        __syncthreads();
        buf ^= 1;
    }

    #pragma unroll
    for (int i = 0; i < 2; i++)
        #pragma unroll
        for (int j = 0; j < 4; j++)
            wmma::store_matrix_sync(C + (size_t)(bm0 + wm * 32 + i * 16) * N + bn0 + wn * 64 + j * 16,
                                    acc[i][j], N, wmma::mem_row_major);
}

// ---------------- block sum helper ----------------
__device__ __forceinline__ float block_sum_256(float v, float* red8)
{
    #pragma unroll
    for (int o = 16; o > 0; o >>= 1) v += __shfl_xor_sync(0xffffffffu, v, o);
    if ((threadIdx.x & 31) == 0) red8[threadIdx.x >> 5] = v;
    __syncthreads();
    float total = 0.0f;
    #pragma unroll
    for (int i = 0; i < 8; i++) total += red8[i];
    return total;
}

// ---------------- RMSNorm(full 5120 row) + RoPE on Q, re-layout to [b,h,s,d] ----------------
__global__ __launch_bounds__(256) void qnorm_rope_kernel(const float* __restrict__ qw,
                                                         const float* __restrict__ cos_h,
                                                         const float* __restrict__ sin_h)
{
    __shared__ float red8[8];
    const int row = blockIdx.x;
    const int b = row >> 11;
    const int s = row & (S_ - 1);
    const float* xr = g_xq + (size_t)row * DIM_;

    float ss = 0.0f;
    for (int i = threadIdx.x; i < DIM_; i += 256) { float v = xr[i]; ss += v * v; }
    float total = block_sum_256(ss, red8);
    const float rms = rsqrtf(total / (float)DIM_ + 1e-6f);

    for (int idx = threadIdx.x; idx < H_ * 64; idx += 256) {
        int h = idx >> 6;
        int d = idx & 63;
        float x1 = xr[h * HD_ + d]      * rms * qw[h * HD_ + d];
        float x2 = xr[h * HD_ + d + 64] * rms * qw[h * HD_ + d + 64];
        float c  = cos_h[s * 64 + d];
        float sn = sin_h[s * 64 + d];
        float* o = g_q + ((size_t)(b * H_ + h) * S_ + s) * HD_;
        o[d]      = x1 * c - x2 * sn;
        o[d + 64] = x2 * c + x1 * sn;
    }
}

// ---------------- RMSNorm(1024) + RoPE on K, copy/relayout V ----------------
__global__ __launch_bounds__(256) void knorm_rope_v_kernel(const float* __restrict__ kw,
                                                           const float* __restrict__ cos_h,
                                                           const float* __restrict__ sin_h)
{
    __shared__ float red8[8];
    const int row = blockIdx.x;
    const int b = row >> 11;
    const int s = row & (S_ - 1);
    const float* xk = g_xk + (size_t)row * KVDIM_;
    const float* xv = g_xv + (size_t)row * KVDIM_;

    float ss = 0.0f;
    for (int i = threadIdx.x; i < KVDIM_; i += 256) { float v = xk[i]; ss += v * v; }
    float total = block_sum_256(ss, red8);
    const float rms = rsqrtf(total / (float)KVDIM_ + 1e-6f);

    for (int idx = threadIdx.x; idx < KVH_ * 64; idx += 256) {
        int h = idx >> 6;
        int d = idx & 63;
        float x1 = xk[h * HD_ + d]      * rms * kw[h * HD_ + d];
        float x2 = xk[h * HD_ + d + 64] * rms * kw[h * HD_ + d + 64];
        float c  = cos_h[s * 64 + d];
        float sn = sin_h[s * 64 + d];
        float* o = g_k + ((size_t)(b * KVH_ + h) * S_ + s) * HD_;
        o[d]      = x1 * c - x2 * sn;
        o[d + 64] = x2 * c + x1 * sn;
    }
    for (int idx = threadIdx.x; idx < KVDIM_; idx += 256) {
        int h = idx >> 7;
        int d = idx & 127;
        g_v[((size_t)(b * KVH_ + h) * S_ + s) * HD_ + d] = xv[idx];
    }
}

// ---------------- flash attention: 64-q x 64-k tiles, WMMA tf32, sliding window ----------------
#define QT 64
#define KT 64
#define HDP 132
#define STP 72
#define ATT_SMEM_FLOATS (4 * QT * HDP + QT * STP + 3 * QT)
#define ATT_SMEM_BYTES  (ATT_SMEM_FLOATS * 4)

__global__ __launch_bounds__(256) void attn_kernel()
{
    extern __shared__ float sm[];
    float* Qs  = sm;                  // 64 x 132
    float* Ks  = Qs + QT * HDP;       // 64 x 132
    float* Vs  = Ks + KT * HDP;       // 64 x 132
    float* Os  = Vs + KT * HDP;       // 64 x 132
    float* Ss  = Os + QT * HDP;       // 64 x 72
    float* m_s = Ss + QT * STP;
    float* l_s = m_s + QT;
    float* al_s = l_s + QT;

    const int q0  = blockIdx.x * QT;
    const int h   = blockIdx.y;
    const int b   = blockIdx.z;
    const int kvh = h / NREP_;
    const int tid = threadIdx.x;
    const int w   = tid >> 5;
    const int wm  = w & 3;
    const int wn  = w >> 2;

    const float* Qg = g_q + ((size_t)(b * H_ + h) * S_ + q0) * HD_;
    const float* Kg = g_k + ((size_t)(b * KVH_ + kvh) * S_) * HD_;
    const float* Vg = g_v + ((size_t)(b * KVH_ + kvh) * S_) * HD_;

    // stage Q tile (tf32)
    #pragma unroll
    for (int i = tid; i < QT * HD_ / 4; i += 256) {
        int r = i >> 5;
        int c = (i & 31) << 2;
        float4 v = *(const float4*)(Qg + (size_t)r * HD_ + c);
        Qs[r * HDP + c + 0] = wmma::__float_to_tf32(v.x);
        Qs[r * HDP + c + 1] = wmma::__float_to_tf32(v.y);
        Qs[r * HDP + c + 2] = wmma::__float_to_tf32(v.z);
        Qs[r * HDP + c + 3] = wmma::__float_to_tf32(v.w);
    }
    for (int i = tid; i < QT * HD_; i += 256) {
        int r = i >> 7;
        Os[r * HDP + (i & 127)] = 0.0f;
    }
    if (tid < QT) { m_s[tid] = -1e30f; l_s[tid] = 0.0f; }
    __syncthreads();

    const int jstart = (q0 >= WINDOW_) ? (q0 - WINDOW_) : 0;
    for (int j0 = jstart; j0 < q0 + QT; j0 += KT) {
        // stage K and V tiles (tf32)
        #pragma unroll
        for (int i = tid; i < KT * HD_ / 4; i += 256) {
            int r = i >> 5;
            int c = (i & 31) << 2;
            float4 kv = *(const float4*)(Kg + (size_t)(j0 + r) * HD_ + c);
            Ks[r * HDP + c + 0] = wmma::__float_to_tf32(kv.x);
            Ks[r * HDP + c + 1] = wmma::__float_to_tf32(kv.y);
            Ks[r * HDP + c + 2] = wmma::__float_to_tf32(kv.z);
            Ks[r * HDP + c + 3] = wmma::__float_to_tf32(kv.w);
            float4 vv = *(const float4*)(Vg + (size_t)(j0 + r) * HD_ + c);
            Vs[r * HDP + c + 0] = wmma::__float_to_tf32(vv.x);
            Vs[r * HDP + c + 1] = wmma::__float_to_tf32(vv.y);
            Vs[r * HDP + c + 2] = wmma::__float_to_tf32(vv.z);
            Vs[r * HDP + c + 3] = wmma::__float_to_tf32(vv.w);
        }
        __syncthreads();

        // ---- S = Q @ K^T (64x64): warp (wm,wn) owns rows 16*wm, cols 32*wn ----
        {
            wmma::fragment<wmma::accumulator, 16, 16, 8, float> sacc[2];
            wmma::fill_fragment(sacc[0], 0.0f);
            wmma::fill_fragment(sacc[1], 0.0f);
            #pragma unroll
            for (int kk = 0; kk < HD_; kk += 8) {
                wmma::fragment<wmma::matrix_a, 16, 16, 8, wmma::precision::tf32, wmma::row_major> af;
                wmma::load_matrix_sync(af, Qs + (wm * 16) * HDP + kk, HDP);
                #pragma unroll
                for (int j = 0; j < 2; j++) {
                    wmma::fragment<wmma::matrix_b, 16, 16, 8, wmma::precision::tf32, wmma::col_major> bf;
                    // B(kk', key) = K[key][kk'] : col-major view of row-major K tile
                    wmma::load_matrix_sync(bf, Ks + (wn * 32 + j * 16) * HDP + kk, HDP);
                    wmma::mma_sync(sacc[j], af, bf, sacc[j]);
                }
            }
            #pragma unroll
            for (int j = 0; j < 2; j++)
                wmma::store_matrix_sync(Ss + (wm * 16) * STP + wn * 32 + j * 16, sacc[j], STP,
                                        wmma::mem_row_major);
        }
        __syncthreads();

        // ---- masked online softmax: 4 threads per row ----
        {
            const int r  = tid >> 2;
            const int l4 = tid & 3;
            const int gi = q0 + r;
            const float mold = m_s[r];
            float pv[16];
            float mx = -1e30f;
            #pragma unroll
            for (int k = 0; k < 16; k++) {
                int c = l4 + (k << 2);
                int gj = j0 + c;
                float sv = Ss[r * STP + c] * SCALE_F;
                bool ok = (gj <= gi) && ((gi - gj) <= WINDOW_);
                sv = ok ? sv : -1e30f;
                pv[k] = sv;
                mx = fmaxf(mx, sv);
            }
            mx = fmaxf(mx, __shfl_xor_sync(0xffffffffu, mx, 1));
            mx = fmaxf(mx, __shfl_xor_sync(0xffffffffu, mx, 2));
            const float mnew = fmaxf(mold, mx);
            float sum = 0.0f;
            #pragma unroll
            for (int k = 0; k < 16; k++) {
                int c = l4 + (k << 2);
                float p = (pv[k] > -5e29f) ? __expf(pv[k] - mnew) : 0.0f;
                sum += p;
                Ss[r * STP + c] = wmma::__float_to_tf32(p);
            }
            sum += __shfl_xor_sync(0xffffffffu, sum, 1);
            sum += __shfl_xor_sync(0xffffffffu, sum, 2);
            if (l4 == 0) {
                float al = __expf(mold - mnew);
                al_s[r] = al;
                l_s[r]  = l_s[r] * al + sum;
                m_s[r]  = mnew;
            }
        }
        __syncthreads();

        // ---- rescale running O ----
        for (int i = tid; i < QT * HD_; i += 256) {
            int r = i >> 7;
            int c = i & 127;
            Os[r * HDP + c] *= al_s[r];
        }
        __syncthreads();

        // ---- O += P @ V : warp (wm,wn) owns rows 16*wm, cols 64*wn ----
        {
            wmma::fragment<wmma::matrix_a, 16, 16, 8, wmma::precision::tf32, wmma::row_major> af[8];
            #pragma unroll
            for (int ki = 0; ki < 8; ki++)
                wmma::load_matrix_sync(af[ki], Ss + (wm * 16) * STP + ki * 8, STP);
            #pragma unroll
            for (int jn = 0; jn < 4; jn++) {
                float* optr = Os + (wm * 16) * HDP + wn * 64 + jn * 16;
                wmma::fragment<wmma::accumulator, 16, 16, 8, float> oc;
                wmma::load_matrix_sync(oc, optr, HDP, wmma::mem_row_major);
                #pragma unroll
                for (int ki = 0; ki < 8; ki++) {
                    wmma::fragment<wmma::matrix_b, 16, 16, 8, wmma::precision::tf32, wmma::row_major> bf;
                    wmma::load_matrix_sync(bf, Vs + (ki * 8) * HDP + wn * 64 + jn * 16, HDP);
                    wmma::mma_sync(oc, af[ki], bf, oc);
                }
                wmma::store_matrix_sync(optr, oc, HDP, wmma::mem_row_major);
            }
        }
        __syncthreads();
    }

    // normalize and write [b, s, h*HD + d]
    for (int i = tid; i < QT * HD_; i += 256) {
        int r = i >> 7;
        int c = i & 127;
        g_attn[((size_t)(b * S_) + q0 + r) * DIM_ + h * HD_ + c] = Os[r * HDP + c] / l_s[r];
    }
}

// ---------------- launch ----------------
extern "C" void kernel_launch(void* const* d_in, const int* in_sizes, int n_in,
                              void* d_out, int out_size)
{
    (void)in_sizes; (void)n_in; (void)out_size;
    const float* x     = (const float*)d_in[0];
    const float* wq    = (const float*)d_in[1];
    const float* wk    = (const float*)d_in[2];
    const float* wv    = (const float*)d_in[3];
    const float* wo    = (const float*)d_in[4];
    const float* qw    = (const float*)d_in[5];
    const float* kw    = (const float*)d_in[6];
    const float* cosh_ = (const float*)d_in[7];
    const float* sinh_ = (const float*)d_in[8];
    float* out = (float*)d_out;

    float *p_xq, *p_xk, *p_xv, *p_attn;
    cudaGetSymbolAddress((void**)&p_xq,   g_xq);
    cudaGetSymbolAddress((void**)&p_xk,   g_xk);
    cudaGetSymbolAddress((void**)&p_xv,   g_xv);
    cudaGetSymbolAddress((void**)&p_attn, g_attn);

    cudaFuncSetAttribute(gemm_tf32,  cudaFuncAttributeMaxDynamicSharedMemorySize, GEMM_SMEM_BYTES);
    cudaFuncSetAttribute(attn_kernel, cudaFuncAttributeMaxDynamicSharedMemorySize, ATT_SMEM_BYTES);

    // QKV projections
    gemm_tf32<<<dim3(DIM_ / BN,   M_ / BM), 256, GEMM_SMEM_BYTES>>>(x, wq, p_xq, M_, DIM_,   DIM_);
    gemm_tf32<<<dim3(KVDIM_ / BN, M_ / BM), 256, GEMM_SMEM_BYTES>>>(x, wk, p_xk, M_, KVDIM_, DIM_);
    gemm_tf32<<<dim3(KVDIM_ / BN, M_ / BM), 256, GEMM_SMEM_BYTES>>>(x, wv, p_xv, M_, KVDIM_, DIM_);

    // norms + rope + relayout
    qnorm_rope_kernel<<<M_, 256>>>(qw, cosh_, sinh_);
    knorm_rope_v_kernel<<<M_, 256>>>(kw, cosh_, sinh_);

    // attention
    attn_kernel<<<dim3(S_ / QT, H_, B_), 256, ATT_SMEM_BYTES>>>();

    // output projection
    gemm_tf32<<<dim3(DIM_ / BN, M_ / BM), 256, GEMM_SMEM_BYTES>>>(p_attn, wo, out, M_, DIM_, DIM_);
}

// round 11
// speedup vs baseline: 1.3939x; 1.3939x over previous
#include <cuda_runtime.h>
#include <cuda_bf16.h>
#include <mma.h>
#include <cstdint>

using namespace nvcuda;

// ---------------- problem constants ----------------
#define B_    2
#define S_    2048
#define DIM_  5120
#define H_    40
#define KVH_  8
#define HD_   128
#define NREP_ 5
#define M_    (B_*S_)        // 4096
#define KVDIM_ (KVH_*HD_)    // 1024
#define QKV_N (DIM_ + 2*KVDIM_)   // 7168
#define WINDOW_ 1024
static const float SCALE_F = (float)(1.2079441541679836 / 11.313708498984760390); // mscale / sqrt(128)

// ---------------- scratch (device globals; no allocations allowed) ----------------
__device__ __align__(256) float g_xr  [(size_t)M_*DIM_];       // tf32-RN-rounded x
__device__ __align__(256) float g_w1  [(size_t)DIM_*QKV_N];    // tf32-RN-rounded concat(wq|wk|wv)
__device__ __align__(256) float g_wo_r[(size_t)DIM_*DIM_];     // tf32-RN-rounded wo
__device__ __align__(256) float g_xqkv[(size_t)M_*QKV_N];      // QKV projection output
__device__ __align__(256) float g_q [(size_t)B_*H_*S_*HD_];
__device__ __align__(256) float g_k [(size_t)B_*KVH_*S_*HD_];
__device__ __align__(256) float g_v [(size_t)B_*KVH_*S_*HD_];
__device__ __align__(256) float g_attn[(size_t)M_*DIM_];       // tf32-RN-rounded attention out

// ================= tf32 WMMA GEMM, 3-stage cp.async pipeline =================
// C[M,N] = A[M,K] @ B[K,N], row-major fp32. Inputs MUST be pre-rounded to tf32-RN
// (cp.async copies raw bits; HMMA's RZ truncation is then lossless).
// CTA tile 128x128, BK=16, 3 stages -> 18,688 B/stage, 56,064 B total => 2 CTAs/SM.
#define BKQ  16
#define BKP  20          // A leading dim (floats); 80 B/row, 16B-aligned
#define BNP  132         // B leading dim (floats); 528 B/row, 16B-aligned
#define A_STG_F (128*BKP)            // 2560 floats
#define B_STG_F (BKQ*BNP)            // 2112 floats
#define STG_F   (A_STG_F + B_STG_F)  // 4672 floats
#define NSTAGE  3
#define GEMM_SMEM (NSTAGE*STG_F*4)   // 56,064 B

__device__ __forceinline__ void cp_async16(void* dst_smem, const void* src_gmem)
{
    uint32_t d = (uint32_t)__cvta_generic_to_shared(dst_smem);
    asm volatile("cp.async.cg.shared.global [%0], [%1], 16;" :: "r"(d), "l"(src_gmem) : "memory");
}

__global__ __launch_bounds__(256, 2) void gemm_tf32(const float* __restrict__ A,
                                                    const float* __restrict__ Bm,
                                                    float* __restrict__ C,
                                                    int N, int K)
{
    extern __shared__ float smem[];
    const int tid = threadIdx.x;
    const int w   = tid >> 5;
    const int wm  = w & 3;      // 0..3 -> 32-row slab
    const int wn  = w >> 2;     // 0..1 -> 64-col slab
    const int bm0 = blockIdx.y * 128;
    const int bn0 = blockIdx.x * 128;
    const int NK  = K >> 4;     // K/16 steps

    wmma::fragment<wmma::accumulator, 16, 16, 8, float> acc[2][4];
    #pragma unroll
    for (int i = 0; i < 2; i++)
        #pragma unroll
        for (int j = 0; j < 4; j++)
            wmma::fill_fragment(acc[i][j], 0.0f);

    // stage loader: 1024 x 16B chunks (A: 512, B: 512), 4 per thread
    auto issue_stage = [&](int s, int k0) {
        float* as = smem + s * STG_F;
        float* bs = as + A_STG_F;
        #pragma unroll
        for (int t = 0; t < 4; t++) {
            int idx = tid + t * 256;
            if (idx < 512) {                       // A: 128 rows x 4 chunks
                int m = idx >> 2, c = (idx & 3) << 2;
                cp_async16(as + m * BKP + c, A + (size_t)(bm0 + m) * K + k0 + c);
            } else {                               // B: 16 k-rows x 32 chunks
                int j = idx - 512;
                int kr = j >> 5, c = (j & 31) << 2;
                cp_async16(bs + kr * BNP + c, Bm + (size_t)(k0 + kr) * N + bn0 + c);
            }
        }
    };

    issue_stage(0, 0);
    asm volatile("cp.async.commit_group;" ::: "memory");
    issue_stage(1, BKQ);
    asm volatile("cp.async.commit_group;" ::: "memory");

    for (int i = 0; i < NK; i++) {
        asm volatile("cp.async.wait_group 1;" ::: "memory");
        __syncthreads();

        const float* as = smem + (i % NSTAGE) * STG_F;
        const float* bs = as + A_STG_F;
        #pragma unroll
        for (int kk = 0; kk < BKQ; kk += 8) {
            wmma::fragment<wmma::matrix_a, 16, 16, 8, wmma::precision::tf32, wmma::row_major> af[2];
            wmma::fragment<wmma::matrix_b, 16, 16, 8, wmma::precision::tf32, wmma::row_major> bf[4];
            #pragma unroll
            for (int x = 0; x < 2; x++)
                wmma::load_matrix_sync(af[x], as + (wm * 32 + x * 16) * BKP + kk, BKP);
            #pragma unroll
            for (int j = 0; j < 4; j++)
                wmma::load_matrix_sync(bf[j], bs + kk * BNP + wn * 64 + j * 16, BNP);
            #pragma unroll
            for (int x = 0; x < 2; x++)
                #pragma unroll
                for (int j = 0; j < 4; j++)
                    wmma::mma_sync(acc[x][j], af[x], bf[j], acc[x][j]);
        }

        const int nx = i + 2;
        if (nx < NK) issue_stage(nx % NSTAGE, nx * BKQ);
        asm volatile("cp.async.commit_group;" ::: "memory");
    }

    #pragma unroll
    for (int x = 0; x < 2; x++)
        #pragma unroll
        for (int j = 0; j < 4; j++)
            wmma::store_matrix_sync(C + (size_t)(bm0 + wm * 32 + x * 16) * N + bn0 + wn * 64 + j * 16,
                                    acc[x][j], N, wmma::mem_row_major);
}

// ================= tf32-RN rounding passes =================
__global__ __launch_bounds__(256) void round_copy(float* __restrict__ dst,
                                                  const float* __restrict__ src, int n4)
{
    int i = blockIdx.x * 256 + threadIdx.x;
    if (i >= n4) return;
    float4 v = ((const float4*)src)[i];
    float4 o;
    o.x = wmma::__float_to_tf32(v.x); o.y = wmma::__float_to_tf32(v.y);
    o.z = wmma::__float_to_tf32(v.z); o.w = wmma::__float_to_tf32(v.w);
    ((float4*)dst)[i] = o;
}

__global__ __launch_bounds__(256) void round_concat_w(const float* __restrict__ wq,
                                                      const float* __restrict__ wk,
                                                      const float* __restrict__ wv)
{
    int i = blockIdx.x * 256 + threadIdx.x;        // float4 index into [5120, 7168]
    const int n4 = DIM_ * QKV_N / 4;
    if (i >= n4) return;
    int c = (i % (QKV_N / 4)) * 4;
    int d = i / (QKV_N / 4);
    const float* src;
    if (c < DIM_)                 src = wq + (size_t)d * DIM_   + c;
    else if (c < DIM_ + KVDIM_)   src = wk + (size_t)d * KVDIM_ + (c - DIM_);
    else                          src = wv + (size_t)d * KVDIM_ + (c - DIM_ - KVDIM_);
    float4 v = *(const float4*)src;
    float4 o;
    o.x = wmma::__float_to_tf32(v.x); o.y = wmma::__float_to_tf32(v.y);
    o.z = wmma::__float_to_tf32(v.z); o.w = wmma::__float_to_tf32(v.w);
    ((float4*)g_w1)[i] = o;
}

// ---------------- block sum helper ----------------
__device__ __forceinline__ float block_sum_256(float v, float* red8)
{
    #pragma unroll
    for (int o = 16; o > 0; o >>= 1) v += __shfl_xor_sync(0xffffffffu, v, o);
    if ((threadIdx.x & 31) == 0) red8[threadIdx.x >> 5] = v;
    __syncthreads();
    float total = 0.0f;
    #pragma unroll
    for (int i = 0; i < 8; i++) total += red8[i];
    return total;
}

// ---------------- RMSNorm(5120) + RoPE on Q, re-layout to [b,h,s,d] ----------------
__global__ __launch_bounds__(256) void qnorm_rope_kernel(const float* __restrict__ qw,
                                                         const float* __restrict__ cos_h,
                                                         const float* __restrict__ sin_h)
{
    __shared__ float red8[8];
    const int row = blockIdx.x;
    const int b = row >> 11;
    const int s = row & (S_ - 1);
    const float* xr = g_xqkv + (size_t)row * QKV_N;

    float ss = 0.0f;
    for (int i = threadIdx.x; i < DIM_; i += 256) { float v = xr[i]; ss += v * v; }
    float total = block_sum_256(ss, red8);
    const float rms = rsqrtf(total / (float)DIM_ + 1e-6f);

    for (int idx = threadIdx.x; idx < H_ * 64; idx += 256) {
        int h = idx >> 6;
        int d = idx & 63;
        float x1 = xr[h * HD_ + d]      * rms * qw[h * HD_ + d];
        float x2 = xr[h * HD_ + d + 64] * rms * qw[h * HD_ + d + 64];
        float c  = cos_h[s * 64 + d];
        float sn = sin_h[s * 64 + d];
        float* o = g_q + ((size_t)(b * H_ + h) * S_ + s) * HD_;
        o[d]      = x1 * c - x2 * sn;
        o[d + 64] = x2 * c + x1 * sn;
    }
}

// ---------------- RMSNorm(1024) + RoPE on K, copy/relayout V ----------------
__global__ __launch_bounds__(256) void knorm_rope_v_kernel(const float* __restrict__ kw,
                                                           const float* __restrict__ cos_h,
                                                           const float* __restrict__ sin_h)
{
    __shared__ float red8[8];
    const int row = blockIdx.x;
    const int b = row >> 11;
    const int s = row & (S_ - 1);
    const float* xk = g_xqkv + (size_t)row * QKV_N + DIM_;
    const float* xv = g_xqkv + (size_t)row * QKV_N + DIM_ + KVDIM_;

    float ss = 0.0f;
    for (int i = threadIdx.x; i < KVDIM_; i += 256) { float v = xk[i]; ss += v * v; }
    float total = block_sum_256(ss, red8);
    const float rms = rsqrtf(total / (float)KVDIM_ + 1e-6f);

    for (int idx = threadIdx.x; idx < KVH_ * 64; idx += 256) {
        int h = idx >> 6;
        int d = idx & 63;
        float x1 = xk[h * HD_ + d]      * rms * kw[h * HD_ + d];
        float x2 = xk[h * HD_ + d + 64] * rms * kw[h * HD_ + d + 64];
        float c  = cos_h[s * 64 + d];
        float sn = sin_h[s * 64 + d];
        float* o = g_k + ((size_t)(b * KVH_ + h) * S_ + s) * HD_;
        o[d]      = x1 * c - x2 * sn;
        o[d + 64] = x2 * c + x1 * sn;
    }
    for (int idx = threadIdx.x; idx < KVDIM_; idx += 256) {
        int h = idx >> 7;
        int d = idx & 127;
        g_v[((size_t)(b * KVH_ + h) * S_ + s) * HD_ + d] = xv[idx];
    }
}

// ---------------- flash attention: 64-q x 64-k tiles, WMMA tf32, sliding window ----------------
#define QT 64
#define KT 64
#define HDP 132
#define STP 72
#define ATT_SMEM_FLOATS (4 * QT * HDP + QT * STP + 3 * QT)
#define ATT_SMEM_BYTES  (ATT_SMEM_FLOATS * 4)

__global__ __launch_bounds__(256) void attn_kernel()
{
    extern __shared__ float sm[];
    float* Qs  = sm;                  // 64 x 132
    float* Ks  = Qs + QT * HDP;       // 64 x 132
    float* Vs  = Ks + KT * HDP;       // 64 x 132
    float* Os  = Vs + KT * HDP;       // 64 x 132
    float* Ss  = Os + QT * HDP;       // 64 x 72
    float* m_s = Ss + QT * STP;
    float* l_s = m_s + QT;
    float* al_s = l_s + QT;

    const int q0  = blockIdx.x * QT;
    const int h   = blockIdx.y;
    const int b   = blockIdx.z;
    const int kvh = h / NREP_;
    const int tid = threadIdx.x;
    const int w   = tid >> 5;
    const int wm  = w & 3;
    const int wn  = w >> 2;

    const float* Qg = g_q + ((size_t)(b * H_ + h) * S_ + q0) * HD_;
    const float* Kg = g_k + ((size_t)(b * KVH_ + kvh) * S_) * HD_;
    const float* Vg = g_v + ((size_t)(b * KVH_ + kvh) * S_) * HD_;

    #pragma unroll
    for (int i = tid; i < QT * HD_ / 4; i += 256) {
        int r = i >> 5;
        int c = (i & 31) << 2;
        float4 v = *(const float4*)(Qg + (size_t)r * HD_ + c);
        Qs[r * HDP + c + 0] = wmma::__float_to_tf32(v.x);
        Qs[r * HDP + c + 1] = wmma::__float_to_tf32(v.y);
        Qs[r * HDP + c + 2] = wmma::__float_to_tf32(v.z);
        Qs[r * HDP + c + 3] = wmma::__float_to_tf32(v.w);
    }
    for (int i = tid; i < QT * HD_; i += 256) {
        int r = i >> 7;
        Os[r * HDP + (i & 127)] = 0.0f;
    }
    if (tid < QT) { m_s[tid] = -1e30f; l_s[tid] = 0.0f; }
    __syncthreads();

    const int jstart = (q0 >= WINDOW_) ? (q0 - WINDOW_) : 0;
    for (int j0 = jstart; j0 < q0 + QT; j0 += KT) {
        #pragma unroll
        for (int i = tid; i < KT * HD_ / 4; i += 256) {
            int r = i >> 5;
            int c = (i & 31) << 2;
            float4 kv = *(const float4*)(Kg + (size_t)(j0 + r) * HD_ + c);
            Ks[r * HDP + c + 0] = wmma::__float_to_tf32(kv.x);
            Ks[r * HDP + c + 1] = wmma::__float_to_tf32(kv.y);
            Ks[r * HDP + c + 2] = wmma::__float_to_tf32(kv.z);
            Ks[r * HDP + c + 3] = wmma::__float_to_tf32(kv.w);
            float4 vv = *(const float4*)(Vg + (size_t)(j0 + r) * HD_ + c);
            Vs[r * HDP + c + 0] = wmma::__float_to_tf32(vv.x);
            Vs[r * HDP + c + 1] = wmma::__float_to_tf32(vv.y);
            Vs[r * HDP + c + 2] = wmma::__float_to_tf32(vv.z);
            Vs[r * HDP + c + 3] = wmma::__float_to_tf32(vv.w);
        }
        __syncthreads();

        // ---- S = Q @ K^T ----
        {
            wmma::fragment<wmma::accumulator, 16, 16, 8, float> sacc[2];
            wmma::fill_fragment(sacc[0], 0.0f);
            wmma::fill_fragment(sacc[1], 0.0f);
            #pragma unroll
            for (int kk = 0; kk < HD_; kk += 8) {
                wmma::fragment<wmma::matrix_a, 16, 16, 8, wmma::precision::tf32, wmma::row_major> af;
                wmma::load_matrix_sync(af, Qs + (wm * 16) * HDP + kk, HDP);
                #pragma unroll
                for (int j = 0; j < 2; j++) {
                    wmma::fragment<wmma::matrix_b, 16, 16, 8, wmma::precision::tf32, wmma::col_major> bf;
                    wmma::load_matrix_sync(bf, Ks + (wn * 32 + j * 16) * HDP + kk, HDP);
                    wmma::mma_sync(sacc[j], af, bf, sacc[j]);
                }
            }
            #pragma unroll
            for (int j = 0; j < 2; j++)
                wmma::store_matrix_sync(Ss + (wm * 16) * STP + wn * 32 + j * 16, sacc[j], STP,
                                        wmma::mem_row_major);
        }
        __syncthreads();

        // ---- masked online softmax: 4 threads per row ----
        {
            const int r  = tid >> 2;
            const int l4 = tid & 3;
            const int gi = q0 + r;
            const float mold = m_s[r];
            float pv[16];
            float mx = -1e30f;
            #pragma unroll
            for (int k = 0; k < 16; k++) {
                int c = l4 + (k << 2);
                int gj = j0 + c;
                float sv = Ss[r * STP + c] * SCALE_F;
                bool ok = (gj <= gi) && ((gi - gj) <= WINDOW_);
                sv = ok ? sv : -1e30f;
                pv[k] = sv;
                mx = fmaxf(mx, sv);
            }
            mx = fmaxf(mx, __shfl_xor_sync(0xffffffffu, mx, 1));
            mx = fmaxf(mx, __shfl_xor_sync(0xffffffffu, mx, 2));
            const float mnew = fmaxf(mold, mx);
            float sum = 0.0f;
            #pragma unroll
            for (int k = 0; k < 16; k++) {
                int c = l4 + (k << 2);
                float p = (pv[k] > -5e29f) ? __expf(pv[k] - mnew) : 0.0f;
                sum += p;
                Ss[r * STP + c] = wmma::__float_to_tf32(p);
            }
            sum += __shfl_xor_sync(0xffffffffu, sum, 1);
            sum += __shfl_xor_sync(0xffffffffu, sum, 2);
            if (l4 == 0) {
                float al = __expf(mold - mnew);
                al_s[r] = al;
                l_s[r]  = l_s[r] * al + sum;
                m_s[r]  = mnew;
            }
        }
        __syncthreads();

        for (int i = tid; i < QT * HD_; i += 256) {
            int r = i >> 7;
            int c = i & 127;
            Os[r * HDP + c] *= al_s[r];
        }
        __syncthreads();

        // ---- O += P @ V ----
        {
            wmma::fragment<wmma::matrix_a, 16, 16, 8, wmma::precision::tf32, wmma::row_major> af[8];
            #pragma unroll
            for (int ki = 0; ki < 8; ki++)
                wmma::load_matrix_sync(af[ki], Ss + (wm * 16) * STP + ki * 8, STP);
            #pragma unroll
            for (int jn = 0; jn < 4; jn++) {
                float* optr = Os + (wm * 16) * HDP + wn * 64 + jn * 16;
                wmma::fragment<wmma::accumulator, 16, 16, 8, float> oc;
                wmma::load_matrix_sync(oc, optr, HDP, wmma::mem_row_major);
                #pragma unroll
                for (int ki = 0; ki < 8; ki++) {
                    wmma::fragment<wmma::matrix_b, 16, 16, 8, wmma::precision::tf32, wmma::row_major> bf;
                    wmma::load_matrix_sync(bf, Vs + (ki * 8) * HDP + wn * 64 + jn * 16, HDP);
                    wmma::mma_sync(oc, af[ki], bf, oc);
                }
                wmma::store_matrix_sync(optr, oc, HDP, wmma::mem_row_major);
            }
        }
        __syncthreads();
    }

    // normalize, round to tf32-RN (feeds wo GEMM via cp.async), write [b, s, h*HD + d]
    for (int i = tid; i < QT * HD_; i += 256) {
        int r = i >> 7;
        int c = i & 127;
        g_attn[((size_t)(b * S_) + q0 + r) * DIM_ + h * HD_ + c] =
            wmma::__float_to_tf32(Os[r * HDP + c] / l_s[r]);
    }
}

// ---------------- launch ----------------
extern "C" void kernel_launch(void* const* d_in, const int* in_sizes, int n_in,
                              void* d_out, int out_size)
{
    (void)in_sizes; (void)n_in; (void)out_size;
    const float* x     = (const float*)d_in[0];
    const float* wq    = (const float*)d_in[1];
    const float* wk    = (const float*)d_in[2];
    const float* wv    = (const float*)d_in[3];
    const float* wo    = (const float*)d_in[4];
    const float* qw    = (const float*)d_in[5];
    const float* kw    = (const float*)d_in[6];
    const float* cosh_ = (const float*)d_in[7];
    const float* sinh_ = (const float*)d_in[8];
    float* out = (float*)d_out;

    float *p_xr, *p_wo_r, *p_w1, *p_xqkv, *p_attn;
    cudaGetSymbolAddress((void**)&p_xr,   g_xr);
    cudaGetSymbolAddress((void**)&p_w1,   g_w1);
    cudaGetSymbolAddress((void**)&p_wo_r, g_wo_r);
    cudaGetSymbolAddress((void**)&p_xqkv, g_xqkv);
    cudaGetSymbolAddress((void**)&p_attn, g_attn);

    cudaFuncSetAttribute(gemm_tf32,   cudaFuncAttributeMaxDynamicSharedMemorySize, GEMM_SMEM);
    cudaFuncSetAttribute(attn_kernel, cudaFuncAttributeMaxDynamicSharedMemorySize, ATT_SMEM_BYTES);

    // tf32-RN pre-rounding (HMMA truncation lossless afterwards)
    {
        int n4x = M_ * DIM_ / 4;
        round_copy<<<(n4x + 255) / 256, 256>>>(p_xr, x, n4x);
        int n4w = DIM_ * QKV_N / 4;
        round_concat_w<<<(n4w + 255) / 256, 256>>>(wq, wk, wv);
        int n4o = DIM_ * DIM_ / 4;
        round_copy<<<(n4o + 255) / 256, 256>>>(p_wo_r, wo, n4o);
    }

    // fused QKV projection: [4096, 7168] = x_r @ concat(wq|wk|wv)
    gemm_tf32<<<dim3(QKV_N / 128, M_ / 128), 256, GEMM_SMEM>>>(p_xr, p_w1, p_xqkv, QKV_N, DIM_);

    // norms + rope + relayout
    qnorm_rope_kernel<<<M_, 256>>>(qw, cosh_, sinh_);
    knorm_rope_v_kernel<<<M_, 256>>>(kw, cosh_, sinh_);

    // attention
    attn_kernel<<<dim3(S_ / QT, H_, B_), 256, ATT_SMEM_BYTES>>>();

    // output projection
    gemm_tf32<<<dim3(DIM_ / 128, M_ / 128), 256, GEMM_SMEM>>>(p_attn, p_wo_r, out, DIM_, DIM_);
}